// round 16
// baseline (speedup 1.0000x reference)
#include <cuda_runtime.h>
#include <cuda_fp16.h>
#include <cstdint>

#define BATCH 4
#define HH 384
#define WW 384
#define NN 128
#define RAD 4
#define NSTEPS 50
#define CLIPMAX 382.999f

// ---------------- scratch ----------------
// fp16 packed quad planes: entry (y,x) = 8 halves {gy,gx} at (y,x),(y,x+1),(y+1,x),(y+1,x+1)
__device__ uint4 g_Gh [BATCH * HH * WW];
__device__ uint4 g_GWh[BATCH * HH * WW];
__device__ float  g_Gc[18];          // gM[0..8], gW[0..8]  (interior-row lattice kernels, R14-verified)
__device__ float2 g_pts[BATCH * NN];
__device__ float  g_wid[BATCH * NN];
__device__ float  g_part[576];
__device__ unsigned g_cnt;

typedef unsigned long long ull;

__device__ __constant__ float C_G[9] = {
    0.027630550874912204f, 0.06628226552596338f, 0.12383156996112883f,
    0.18017411419619135f,  0.20416299888360846f, 0.18017411419619135f,
    0.12383156996112883f,  0.06628226552596338f, 0.027630550874912204f };
__device__ __constant__ float C_DG[9] = {
    0.027630550874912204f,  0.049711699144472535f,  0.061915784980564414f,
    0.04504352854904784f,   0.0f,                  -0.04504352854904784f,
   -0.061915784980564414f, -0.049711699144472535f, -0.027630550874912204f };

__device__ __forceinline__ float fsqrt_approx(float x) {
    float r; asm("sqrt.approx.f32 %0, %1;" : "=f"(r) : "f"(x)); return r;
}
__device__ __forceinline__ ull pack2(float lo, float hi) {
    ull r; asm("mov.b64 %0, {%1, %2};" : "=l"(r) : "f"(lo), "f"(hi)); return r;
}
__device__ __forceinline__ float2 unpack2(ull v) {
    float2 r; asm("mov.b64 {%0, %1}, %2;" : "=f"(r.x), "=f"(r.y) : "l"(v)); return r;
}
__device__ __forceinline__ void ffma2(ull& d, ull a, ull b) {
    asm("fma.rn.f32x2 %0, %1, %2, %0;" : "+l"(d) : "l"(a), "l"(b));
}

// fp16 quad bilinear: ONE LDG.128 per tap
__device__ __forceinline__ float2 bilin_h(const uint4* __restrict__ plane, float y, float x) {
    y = fminf(fmaxf(y, 0.f), CLIPMAX);
    x = fminf(fmaxf(x, 0.f), CLIPMAX);
    float fy = floorf(y), fx = floorf(x);
    int   y0 = (int)fy,  x0 = (int)fx;
    float wy = y - fy,   wx = x - fx;
    uint4 q = __ldg(plane + y0 * WW + x0);
    const __half2* h = reinterpret_cast<const __half2*>(&q);
    float2 q00 = __half22float2(h[0]);
    float2 q01 = __half22float2(h[1]);
    float2 q10 = __half22float2(h[2]);
    float2 q11 = __half22float2(h[3]);
    float w00 = (1.f - wy) * (1.f - wx);
    float w01 = (1.f - wy) * wx;
    float w10 = wy * (1.f - wx);
    float w11 = wy * wx;
    float2 r;
    r.x = q00.x * w00 + q01.x * w01 + q10.x * w10 + q11.x * w11;
    r.y = q00.y * w00 + q01.y * w01 + q10.y * w10 + q11.y * w11;
    return r;
}

// ---------------- kernel 1: conv -> fp16 quad planes, + lattice kernel coefficients ----------------
__global__ void __launch_bounds__(256) prep_kernel(const float* __restrict__ pred) {
    const int bid = blockIdx.x;
    const int tid = threadIdx.x;

    if (bid < 576) {
        __shared__ union { float2 tile[41][41]; float4 res[34][34]; } U;
        __shared__ float4 hs[41][33];

        const int bx = (bid % 12) * 32;
        const int by = ((bid / 12) % 12) * 32;
        const int b  = bid / 144;
        const float* img = pred + b * HH * WW;

        for (int i = tid; i < 41 * 41; i += 256) {
            int ly = i / 41, lx = i % 41;
            int gy = by - RAD + ly, gx = bx - RAD + lx;
            float v = (gy >= 0 && gy < HH && gx >= 0 && gx < WW) ? img[gy * WW + gx] : 0.f;
            U.tile[ly][lx] = make_float2(v, fabsf(v));
        }
        __syncthreads();

        for (int i = tid; i < 41 * 33; i += 256) {
            int r = i / 33, c = i % 33;
            float hgp = 0.f, hdp = 0.f, hga = 0.f, hda = 0.f;
#pragma unroll
            for (int kx = 0; kx < 9; kx++) {
                float2 v = U.tile[r][c + kx];
                hgp = fmaf(C_G[kx],  v.x, hgp);
                hdp = fmaf(C_DG[kx], v.x, hdp);
                hga = fmaf(C_G[kx],  v.y, hga);
                hda = fmaf(C_DG[kx], v.y, hda);
            }
            hs[r][c] = make_float4(hgp, hdp, hga, hda);
        }
        __syncthreads();

        for (int i = tid; i < 33 * 33; i += 256) {
            int r = i / 33, c = i % 33;
            float c0p = 0.f, c1p = 0.f, c0a = 0.f, c1a = 0.f;
#pragma unroll
            for (int ky = 0; ky < 9; ky++) {
                float4 h = hs[r + ky][c];
                c0p = fmaf(C_DG[ky], h.x, c0p);
                c1p = fmaf(C_G[ky],  h.y, c1p);
                c0a = fmaf(C_DG[ky], h.z, c0a);
                c1a = fmaf(C_G[ky],  h.w, c1a);
            }
            U.res[r][c] = make_float4(10.f * c0p, 10.f * c1p, 10.f * c0a, 10.f * c1a);
        }
        __syncthreads();

        const int tx = tid & 31, ty = tid >> 5;
#pragma unroll
        for (int s4 = 0; s4 < 4; s4++) {
            int oy = ty + s4 * 8;
            float4 A = U.res[oy][tx],     B = U.res[oy][tx + 1];
            float4 C = U.res[oy + 1][tx], D = U.res[oy + 1][tx + 1];
            uint4 qg, qw;
            __half2* pg = reinterpret_cast<__half2*>(&qg);
            __half2* pw = reinterpret_cast<__half2*>(&qw);
            pg[0] = __float22half2_rn(make_float2(A.x, A.y));
            pg[1] = __float22half2_rn(make_float2(B.x, B.y));
            pg[2] = __float22half2_rn(make_float2(C.x, C.y));
            pg[3] = __float22half2_rn(make_float2(D.x, D.y));
            pw[0] = __float22half2_rn(make_float2(A.z, A.w));
            pw[1] = __float22half2_rn(make_float2(B.z, B.w));
            pw[2] = __float22half2_rn(make_float2(C.z, C.w));
            pw[3] = __float22half2_rn(make_float2(D.z, D.w));
            const int o = (b * HH + by + oy) * WW + bx + tx;
            g_Gh [o] = qg;
            g_GWh[o] = qw;
        }
    } else {
        // lattice kernel = interior row 64 of the true M / Mw (R14-verified):
        // g[d] = sum_k eps_k/128 * f(lam_k) * cos(pi k 129/256) * cos(pi k (129+2d)/256)
        if (tid < 18) {
            int  d   = tid % 9;
            bool isM = tid < 9;
            float s = 0.f;
            for (int k = 0; k < 128; k++) {
                float lam = 2.f - 2.f * cospif((float)k / 128.f);
                float f = isM ? 1.f / (1.f + 0.001f * lam + 0.001f * lam * lam)
                              : 1.f / (1.f + 0.001f * lam);
                float eps = (k == 0) ? 1.f : 2.f;
                float ci = cospif((float)(k * 129) / 256.f);
                float cj = cospif((float)(k * (129 + 2 * d)) / 256.f);
                s = fmaf(eps * 0.0078125f * f, ci * cj, s);
            }
            g_Gc[tid] = s;
        }
        if (tid == 18) g_cnt = 0;
    }
}

// ---------------- kernel 2: snake — ONE WARP per sample, zero block barriers ----------------
// Lane l owns nodes 4l..4l+3. Halo via warp-private smem pads + __syncwarp.
// Lattice-kernel conv (9 coeffs) with reflection pads. R11 lag schedule:
// iter k computes pts_k and wid_{k-1}; gathers at pts_k issued after the pts conv,
// consumed next iteration. Epilogue computes wid_50.
__global__ void __launch_bounds__(32) snake_kernel(const float* __restrict__ nodes) {
    const int b = blockIdx.x;
    const int l = threadIdx.x;

    __shared__ __align__(16) ull   v2pad[2][NN + 16];   // idx = 8 + node; pads = reflections
    __shared__ __align__(16) float vwpad[2][NN + 16];

    ull   Gm[9];
    float Gw[9];
#pragma unroll
    for (int d = 0; d < 9; d++) {
        float g = __ldg(&g_Gc[d]);
        Gm[d] = pack2(g, g);
        Gw[d] = __ldg(&g_Gc[9 + d]);
    }

    const uint4* Gp  = g_Gh  + b * HH * WW;
    const uint4* GWp = g_GWh + b * HH * WW;

    float2 p[4], f[4], fw[4];
    float  wd[4] = {1.f, 1.f, 1.f, 1.f};
    {
        const float4* np = reinterpret_cast<const float4*>(nodes + (b * NN + 4 * l) * 2);
        float4 a = __ldg(np), c = __ldg(np + 1);
        p[0] = make_float2(a.x, a.y); p[1] = make_float2(a.z, a.w);
        p[2] = make_float2(c.x, c.y); p[3] = make_float2(c.z, c.w);
    }
#pragma unroll
    for (int n = 0; n < 4; n++) { f[n] = bilin_h(Gp, p[n].x, p[n].y); fw[n] = bilin_h(GWp, p[n].x, p[n].y); }

    for (int k = 1; k <= NSTEPS; k++) {
        const int buf = k & 1;
        ull v2[4]; float vw[4];
#pragma unroll
        for (int n = 0; n < 4; n++) {
            v2[n] = pack2(p[n].x + 0.1f * f[n].x, p[n].y + 0.1f * f[n].y);
            vw[n] = wd[n] + 0.1f * sqrtf(fw[n].x * fw[n].x + fw[n].y * fw[n].y);
        }
        __syncwarp();     // prior buf reads (2 iters ago) done before overwrite
#pragma unroll
        for (int n = 0; n < 4; n++) {
            v2pad[buf][8 + 4 * l + n] = v2[n];
            vwpad[buf][8 + 4 * l + n] = vw[n];
        }
        if (l < 2) {
#pragma unroll
            for (int n = 0; n < 4; n++) {
                v2pad[buf][7 - (4 * l + n)] = v2[n];      // left reflection
                vwpad[buf][7 - (4 * l + n)] = vw[n];
            }
        }
        if (l >= 30) {
#pragma unroll
            for (int n = 0; n < 4; n++) {
                v2pad[buf][263 - (4 * l + n)] = v2[n];    // right reflection
                vwpad[buf][263 - (4 * l + n)] = vw[n];
            }
        }
        __syncwarp();

        // pts conv (17 taps, shared kernel)
        {
            ull W[20];
#pragma unroll
            for (int q = 0; q < 10; q++) {
                ulonglong2 t2 = *reinterpret_cast<const ulonglong2*>(&v2pad[buf][4 * l + 2 * q]);
                W[2 * q] = t2.x; W[2 * q + 1] = t2.y;
            }
            ull acc[4] = {0ull, 0ull, 0ull, 0ull};
#pragma unroll
            for (int u = 0; u < 17; u++) {
                ull cc = Gm[u < 8 ? 8 - u : u - 8];
#pragma unroll
                for (int n = 0; n < 4; n++) ffma2(acc[n], cc, W[n + u]);
            }
#pragma unroll
            for (int n = 0; n < 4; n++) p[n] = unpack2(acc[n]);
        }

        // issue next-iteration gathers immediately (8 independent LDG.128 -> MLP)
        if (k < NSTEPS) {
#pragma unroll
            for (int n = 0; n < 4; n++) f[n]  = bilin_h(Gp,  p[n].x, p[n].y);
        }
#pragma unroll
        for (int n = 0; n < 4; n++) fw[n] = bilin_h(GWp, p[n].x, p[n].y);

        // width conv (computes wid_{k-1}; k==1 result discarded, wid_0 = 1)
        {
            float Wf[20];
#pragma unroll
            for (int q = 0; q < 5; q++) {
                float4 t4 = *reinterpret_cast<const float4*>(&vwpad[buf][4 * l + 4 * q]);
                Wf[4 * q] = t4.x; Wf[4 * q + 1] = t4.y; Wf[4 * q + 2] = t4.z; Wf[4 * q + 3] = t4.w;
            }
            float aw[4] = {0.f, 0.f, 0.f, 0.f};
#pragma unroll
            for (int u = 0; u < 17; u++) {
                float cc = Gw[u < 8 ? 8 - u : u - 8];
#pragma unroll
                for (int n = 0; n < 4; n++) aw[n] = fmaf(cc, Wf[n + u], aw[n]);
            }
            if (k > 1) {
#pragma unroll
                for (int n = 0; n < 4; n++) wd[n] = aw[n];
            }
        }
    }

    // epilogue: wid_50 = Mw @ (wid_49 + 0.1*||GW(pts_50)||)
    {
        const int buf = (NSTEPS + 1) & 1;
        float vw[4];
#pragma unroll
        for (int n = 0; n < 4; n++) vw[n] = wd[n] + 0.1f * sqrtf(fw[n].x * fw[n].x + fw[n].y * fw[n].y);
        __syncwarp();
#pragma unroll
        for (int n = 0; n < 4; n++) vwpad[buf][8 + 4 * l + n] = vw[n];
        if (l < 2) {
#pragma unroll
            for (int n = 0; n < 4; n++) vwpad[buf][7 - (4 * l + n)] = vw[n];
        }
        if (l >= 30) {
#pragma unroll
            for (int n = 0; n < 4; n++) vwpad[buf][263 - (4 * l + n)] = vw[n];
        }
        __syncwarp();
        float Wf[20];
#pragma unroll
        for (int q = 0; q < 5; q++) {
            float4 t4 = *reinterpret_cast<const float4*>(&vwpad[buf][4 * l + 4 * q]);
            Wf[4 * q] = t4.x; Wf[4 * q + 1] = t4.y; Wf[4 * q + 2] = t4.z; Wf[4 * q + 3] = t4.w;
        }
        float aw[4] = {0.f, 0.f, 0.f, 0.f};
#pragma unroll
        for (int u = 0; u < 17; u++) {
            float cc = Gw[u < 8 ? 8 - u : u - 8];
#pragma unroll
            for (int n = 0; n < 4; n++) aw[n] = fmaf(cc, Wf[n + u], aw[n]);
        }
#pragma unroll
        for (int n = 0; n < 4; n++) wd[n] = aw[n];
    }

#pragma unroll
    for (int n = 0; n < 4; n++) {
        g_pts[b * NN + 4 * l + n] = p[n];
        g_wid[b * NN + 4 * l + n] = wd[n];
    }
}

// ---------------- kernel 3: render + shortlist + fused final reduce ----------------
__global__ void __launch_bounds__(256) render_kernel(const float* __restrict__ pred,
                                                     float* __restrict__ out) {
    const int b  = blockIdx.z;
    const int x0 = blockIdx.x * 32;
    const int y0 = blockIdx.y * 32;
    const int t  = threadIdx.x;

    __shared__ float4 keep[NN];
    __shared__ float  ur[NN];
    __shared__ int    wcnt[4], wofs[4], cnt;
    __shared__ float  ublim;

    float lb = 0.f; float4 nd = make_float4(0, 0, 0, 0); unsigned bmask = 0; bool pred_k = false;
    const float cy = (float)y0 + 15.5f, cx = (float)x0 + 15.5f;
    const float R = 21.95f;
    if (t < NN) {
        float2 p = g_pts[b * NN + t];
        float w  = g_wid[b * NN + t];
        nd = make_float4(p.x, p.y, w, 0.f);
        float dy = p.x - cy, dx = p.y - cx;
        float cd = sqrtf(dy * dy + dx * dx);
        lb = cd - R - w;
        ur[t] = cd + R - w;
    }
    __syncthreads();
    if (t < 64) ur[t] = fminf(ur[t], ur[t + 64]);
    __syncthreads();
    if (t < 32) {
        float v = fminf(ur[t], ur[t + 32]);
#pragma unroll
        for (int s = 16; s > 0; s >>= 1) v = fminf(v, __shfl_xor_sync(0xffffffffu, v, s));
        if (t == 0) ublim = fminf(v, 15.0f) + 0.02f;
    }
    __syncthreads();

    if (t < NN) {
        pred_k = lb < ublim;
        bmask = __ballot_sync(0xffffffffu, pred_k);
        if ((t & 31) == 0) wcnt[t >> 5] = __popc(bmask);
    }
    __syncthreads();
    if (t == 0) {
        int o = 0;
#pragma unroll
        for (int w = 0; w < 4; w++) { wofs[w] = o; o += wcnt[w]; }
        cnt = o;
    }
    __syncthreads();
    if (t < NN && pred_k) {
        int pos = wofs[t >> 5] + __popc(bmask & ((1u << (t & 31)) - 1u));
        keep[pos] = nd;
    }
    __syncthreads();

    const int n = cnt;
    const int y  = y0 + (t >> 3);
    const int xg = x0 + (t & 7) * 4;
    const float fy = (float)y, fx0 = (float)xg;
    const float mub = ublim;
    float m0 = mub, m1 = mub, m2 = mub, m3 = mub;

    for (int k = 0; k < n; k++) {
        float4 kk = keep[k];
        float dy  = fy - kk.x;
        float dy2 = dy * dy;
        float dx0 = fx0 - kk.y;
        float dx1 = dx0 + 1.f, dx2 = dx0 + 2.f, dx3 = dx0 + 3.f;
        float d20 = fmaf(dx0, dx0, dy2);
        float d21 = fmaf(dx1, dx1, dy2);
        float d22 = fmaf(dx2, dx2, dy2);
        float d23 = fmaf(dx3, dx3, dy2);
        float t0 = m0 + kk.z, t1 = m1 + kk.z, t2 = m2 + kk.z, t3 = m3 + kk.z;
        bool imp = (t0 > 0.f && d20 < t0 * t0) || (t1 > 0.f && d21 < t1 * t1) ||
                   (t2 > 0.f && d22 < t2 * t2) || (t3 > 0.f && d23 < t3 * t3);
        if (__any_sync(0xffffffffu, imp)) {
            m0 = fminf(m0, fsqrt_approx(d20) - kk.z);
            m1 = fminf(m1, fsqrt_approx(d21) - kk.z);
            m2 = fminf(m2, fsqrt_approx(d22) - kk.z);
            m3 = fminf(m3, fsqrt_approx(d23) - kk.z);
        }
    }
    m0 = fminf(fmaxf(m0, 0.f), 15.f);
    m1 = fminf(fmaxf(m1, 0.f), 15.f);
    m2 = fminf(fmaxf(m2, 0.f), 15.f);
    m3 = fminf(fmaxf(m3, 0.f), 15.f);

    const float4 pv = *reinterpret_cast<const float4*>(pred + (b * HH + y) * WW + xg);
    float e0 = pv.x - m0, e1 = pv.y - m1, e2 = pv.z - m2, e3 = pv.w - m3;
    float e = e0 * e0 + e1 * e1 + e2 * e2 + e3 * e3;

    __shared__ float red[256];
    red[t] = e;
    __syncthreads();
    if (t < 128) red[t] += red[t + 128];
    __syncthreads();
    if (t < 64) red[t] += red[t + 64];
    __syncthreads();
    if (t < 32) {
        float v = red[t] + red[t + 32];
#pragma unroll
        for (int s = 16; s > 0; s >>= 1) v += __shfl_down_sync(0xffffffffu, v, s);
        if (t == 0) g_part[(b * 12 + blockIdx.y) * 12 + blockIdx.x] = v;
    }

    __shared__ bool amLast;
    if (t == 0) {
        __threadfence();
        unsigned v = atomicAdd(&g_cnt, 1u);
        amLast = (v == 575u);
    }
    __syncthreads();
    if (amLast) {
        __shared__ double sh[256];
        double s = 0.0;
        for (int idx = t; idx < 576; idx += 256) s += (double)g_part[idx];
        sh[t] = s;
        __syncthreads();
        for (int st = 128; st > 0; st >>= 1) {
            if (t < st) sh[t] += sh[t + st];
            __syncthreads();
        }
        if (t == 0) out[0] = (float)(sh[0] / (double)(BATCH * HH * WW));
    }
}

// ---------------- launcher ----------------
extern "C" void kernel_launch(void* const* d_in, const int* in_sizes, int n_in,
                              void* d_out, int out_size) {
    const float* pred  = (const float*)d_in[0];
    const float* nodes = (const float*)d_in[1];
    float* out = (float*)d_out;
    (void)in_sizes; (void)n_in; (void)out_size;

    prep_kernel<<<577, 256>>>(pred);
    snake_kernel<<<BATCH, 32>>>(nodes);
    render_kernel<<<dim3(12, 12, BATCH), 256>>>(pred, out);
}

// round 17
// speedup vs baseline: 1.3539x; 1.3539x over previous
#include <cuda_runtime.h>
#include <cuda_fp16.h>
#include <cstdint>

#define BATCH 4
#define HH 384
#define WW 384
#define NN 128
#define RAD 4
#define NSTEPS 50
#define CLIPMAX 382.999f
#define HB 8
#define BW (2 * HB + 1)

// ---------------- scratch ----------------
// fp16 packed quad planes: entry (y,x) = 8 halves {gy,gx} at (y,x),(y,x+1),(y+1,x),(y+1,x+1)
__device__ uint4 g_Gh [BATCH * HH * WW];
__device__ uint4 g_GWh[BATCH * HH * WW];
__device__ float  g_M [NN * NN];
__device__ float  g_Mw[NN * NN];
__device__ float2 g_pts[BATCH * NN];
__device__ float  g_wid[BATCH * NN];
__device__ float  g_part[576];
__device__ unsigned g_cnt;

typedef unsigned long long ull;

__device__ __constant__ float C_G[9] = {
    0.027630550874912204f, 0.06628226552596338f, 0.12383156996112883f,
    0.18017411419619135f,  0.20416299888360846f, 0.18017411419619135f,
    0.12383156996112883f,  0.06628226552596338f, 0.027630550874912204f };
__device__ __constant__ float C_DG[9] = {
    0.027630550874912204f,  0.049711699144472535f,  0.061915784980564414f,
    0.04504352854904784f,   0.0f,                  -0.04504352854904784f,
   -0.061915784980564414f, -0.049711699144472535f, -0.027630550874912204f };

__device__ __forceinline__ float fsqrt_approx(float x) {
    float r; asm("sqrt.approx.f32 %0, %1;" : "=f"(r) : "f"(x)); return r;
}
__device__ __forceinline__ ull pack2(float lo, float hi) {
    ull r; asm("mov.b64 %0, {%1, %2};" : "=l"(r) : "f"(lo), "f"(hi)); return r;
}
__device__ __forceinline__ float2 unpack2(ull v) {
    float2 r; asm("mov.b64 {%0, %1}, %2;" : "=f"(r.x), "=f"(r.y) : "l"(v)); return r;
}
__device__ __forceinline__ void ffma2(ull& d, ull a, ull b) {
    asm("fma.rn.f32x2 %0, %1, %2, %0;" : "+l"(d) : "l"(a), "l"(b));
}

// fp16 quad bilinear: ONE LDG.128 per tap
__device__ __forceinline__ float2 bilin_h(const uint4* __restrict__ plane, float y, float x) {
    y = fminf(fmaxf(y, 0.f), CLIPMAX);
    x = fminf(fmaxf(x, 0.f), CLIPMAX);
    float fy = floorf(y), fx = floorf(x);
    int   y0 = (int)fy,  x0 = (int)fx;
    float wy = y - fy,   wx = x - fx;
    uint4 q = __ldg(plane + y0 * WW + x0);
    const __half2* h = reinterpret_cast<const __half2*>(&q);
    float2 q00 = __half22float2(h[0]);
    float2 q01 = __half22float2(h[1]);
    float2 q10 = __half22float2(h[2]);
    float2 q11 = __half22float2(h[3]);
    float w00 = (1.f - wy) * (1.f - wx);
    float w01 = (1.f - wy) * wx;
    float w10 = wy * (1.f - wx);
    float w11 = wy * wx;
    float2 r;
    r.x = q00.x * w00 + q01.x * w01 + q10.x * w10 + q11.x * w11;
    r.y = q00.y * w00 + q01.y * w01 + q10.y * w10 + q11.y * w11;
    return r;
}

// ---------------- kernel 1: separable conv -> fp16 quad planes, + matgen (512 thr) ----------------
__global__ void __launch_bounds__(512) prep_kernel(const float* __restrict__ pred) {
    const int bid = blockIdx.x;
    const int tid = threadIdx.x;

    if (bid < 576) {
        __shared__ union { float2 tile[41][41]; float4 res[34][34]; } U;
        __shared__ float4 hs[41][33];

        const int bx = (bid % 12) * 32;
        const int by = ((bid / 12) % 12) * 32;
        const int b  = bid / 144;
        const float* img = pred + b * HH * WW;

        for (int i = tid; i < 41 * 41; i += 512) {
            int ly = i / 41, lx = i % 41;
            int gy = by - RAD + ly, gx = bx - RAD + lx;
            float v = (gy >= 0 && gy < HH && gx >= 0 && gx < WW) ? img[gy * WW + gx] : 0.f;
            U.tile[ly][lx] = make_float2(v, fabsf(v));
        }
        __syncthreads();

        for (int i = tid; i < 41 * 33; i += 512) {
            int r = i / 33, c = i % 33;
            float hgp = 0.f, hdp = 0.f, hga = 0.f, hda = 0.f;
#pragma unroll
            for (int kx = 0; kx < 9; kx++) {
                float2 v = U.tile[r][c + kx];
                hgp = fmaf(C_G[kx],  v.x, hgp);
                hdp = fmaf(C_DG[kx], v.x, hdp);
                hga = fmaf(C_G[kx],  v.y, hga);
                hda = fmaf(C_DG[kx], v.y, hda);
            }
            hs[r][c] = make_float4(hgp, hdp, hga, hda);
        }
        __syncthreads();

        for (int i = tid; i < 33 * 33; i += 512) {
            int r = i / 33, c = i % 33;
            float c0p = 0.f, c1p = 0.f, c0a = 0.f, c1a = 0.f;
#pragma unroll
            for (int ky = 0; ky < 9; ky++) {
                float4 h = hs[r + ky][c];
                c0p = fmaf(C_DG[ky], h.x, c0p);
                c1p = fmaf(C_G[ky],  h.y, c1p);
                c0a = fmaf(C_DG[ky], h.z, c0a);
                c1a = fmaf(C_G[ky],  h.w, c1a);
            }
            U.res[r][c] = make_float4(10.f * c0p, 10.f * c1p, 10.f * c0a, 10.f * c1a);
        }
        __syncthreads();

        // pack fp16 quads: ty spans 16 rows, 2 passes
        const int tx = tid & 31, ty = tid >> 5;
#pragma unroll
        for (int s4 = 0; s4 < 2; s4++) {
            int oy = ty + s4 * 16;
            float4 A = U.res[oy][tx],     B = U.res[oy][tx + 1];
            float4 C = U.res[oy + 1][tx], D = U.res[oy + 1][tx + 1];
            uint4 qg, qw;
            __half2* pg = reinterpret_cast<__half2*>(&qg);
            __half2* pw = reinterpret_cast<__half2*>(&qw);
            pg[0] = __float22half2_rn(make_float2(A.x, A.y));
            pg[1] = __float22half2_rn(make_float2(B.x, B.y));
            pg[2] = __float22half2_rn(make_float2(C.x, C.y));
            pg[3] = __float22half2_rn(make_float2(D.x, D.y));
            pw[0] = __float22half2_rn(make_float2(A.z, A.w));
            pw[1] = __float22half2_rn(make_float2(B.z, B.w));
            pw[2] = __float22half2_rn(make_float2(C.z, C.w));
            pw[3] = __float22half2_rn(make_float2(D.z, D.w));
            const int o = (b * HH + by + oy) * WW + bx + tx;
            g_Gh [o] = qg;
            g_GWh[o] = qw;
        }
    } else {
        // ---- matgen: M, Mw via DCT eigenbasis (first 256 threads only) ----
        __shared__ float am[2][NN], aw[2][NN];
        if (bid == 576 && tid == 0) g_cnt = 0;
        if (tid < 256) {
            const int h = tid >> 7;
            const int i = (bid - 576) * 2 + h;
            const int j = tid & 127;
            {
                int k = j;
                float lam = 2.f - 2.f * cospif((float)k / 128.f);
                float c2  = (k == 0 ? 1.f : 2.f) / 128.f;
                float dm  = 1.f / (1.f + 0.001f * lam + 0.001f * lam * lam);
                float dw  = 1.f / (1.f + 0.001f * lam);
                float a   = cospif((float)(k * (2 * i + 1)) / 256.f);
                am[h][k] = c2 * dm * a;
                aw[h][k] = c2 * dw * a;
            }
            __syncthreads();
            float sm = 0.f, sw = 0.f;
#pragma unroll 4
            for (int k = 0; k < NN; k++) {
                float bq = cospif((float)(k * (2 * j + 1)) / 256.f);
                sm = fmaf(am[h][k], bq, sm);
                sw = fmaf(aw[h][k], bq, sw);
            }
            g_M [i * NN + j] = sm;
            g_Mw[i * NN + j] = sw;
        } else {
            __syncthreads();
        }
    }
}

// ---------------- kernel 2: snake (R11 pipelined pair-split, verbatim) ----------------
__global__ void __launch_bounds__(256) snake_kernel(const float* __restrict__ nodes) {
    const int b   = blockIdx.x;
    const int tid = threadIdx.x;
    const int i   = tid >> 1;
    const int h   = tid & 1;

    __shared__ __align__(16) float2 v2pad[2][NN + 2 * HB];
    __shared__ __align__(16) float  vwpad[2][NN + 2 * HB];

    if (tid < HB) {
#pragma unroll
        for (int s = 0; s < 2; s++) {
            v2pad[s][tid] = make_float2(0.f, 0.f);
            v2pad[s][NN + HB + tid] = make_float2(0.f, 0.f);
            vwpad[s][tid] = 0.f;
            vwpad[s][NN + HB + tid] = 0.f;
        }
    }

    ull   Mp[9];
    float Mwr[9];
#pragma unroll
    for (int uu = 0; uu < 9; uu++) {
        int u = 2 * uu + h;
        float m = 0.f, mw = 0.f;
        if (u < BW) {
            int j = i - HB + u;
            bool ok = (j >= 0) && (j < NN);
            m  = ok ? __ldg(&g_M [i * NN + j]) : 0.f;
            mw = ok ? __ldg(&g_Mw[i * NN + j]) : 0.f;
        }
        Mp[uu]  = pack2(m, m);
        Mwr[uu] = mw;
    }

    const uint4* Gb    = g_Gh  + b * HH * WW;
    const uint4* GWb   = g_GWh + b * HH * WW;
    const uint4* plane = h ? GWb : Gb;

    float2 p = make_float2(__ldg(&nodes[(b * NN + i) * 2]), __ldg(&nodes[(b * NN + i) * 2 + 1]));
    float  wd = 1.f;

    float2 gres = bilin_h(plane, p.x, p.y);
    __syncthreads();

#pragma unroll 2
    for (int k = 1; k <= NSTEPS; k++) {
        const int buf = k & 1;
        if (h == 0)
            v2pad[buf][HB + i] = make_float2(p.x + 0.1f * gres.x, p.y + 0.1f * gres.y);
        else
            vwpad[buf][HB + i] = wd + 0.1f * sqrtf(gres.x * gres.x + gres.y * gres.y);
        __syncthreads();

        const ull* v2u = reinterpret_cast<const ull*>(v2pad[buf]);
        ull acc = 0ull;
#pragma unroll
        for (int uu = 0; uu < 9; uu++) {
            int u = 2 * uu + h;
            if (u < BW) ffma2(acc, Mp[uu], v2u[i + u]);
        }
        float2 pa = unpack2(acc);
        pa.x += __shfl_xor_sync(0xffffffffu, pa.x, 1);
        pa.y += __shfl_xor_sync(0xffffffffu, pa.y, 1);
        p = pa;

        gres = bilin_h(plane, p.x, p.y);

        const float* vw = vwpad[buf];
        float wacc = 0.f;
#pragma unroll
        for (int uu = 0; uu < 9; uu++) {
            int u = 2 * uu + h;
            if (u < BW) wacc = fmaf(Mwr[uu], vw[i + u], wacc);
        }
        wacc += __shfl_xor_sync(0xffffffffu, wacc, 1);
        if (k > 1) wd = wacc;
    }

    {
        const int buf = (NSTEPS + 1) & 1;
        if (h == 1)
            vwpad[buf][HB + i] = wd + 0.1f * sqrtf(gres.x * gres.x + gres.y * gres.y);
        __syncthreads();
        const float* vw = vwpad[buf];
        float wacc = 0.f;
#pragma unroll
        for (int uu = 0; uu < 9; uu++) {
            int u = 2 * uu + h;
            if (u < BW) wacc = fmaf(Mwr[uu], vw[i + u], wacc);
        }
        wacc += __shfl_xor_sync(0xffffffffu, wacc, 1);
        wd = wacc;
    }

    if (h == 0) g_pts[b * NN + i] = p;
    else        g_wid[b * NN + i] = wd;
}

// ---------------- kernel 3: render + shortlist + fused final reduce (R11 verbatim) ----------------
__global__ void __launch_bounds__(256) render_kernel(const float* __restrict__ pred,
                                                     float* __restrict__ out) {
    const int b  = blockIdx.z;
    const int x0 = blockIdx.x * 32;
    const int y0 = blockIdx.y * 32;
    const int t  = threadIdx.x;

    __shared__ float4 keep[NN];
    __shared__ float  ur[NN];
    __shared__ int    wcnt[4], wofs[4], cnt;
    __shared__ float  ublim;

    float lb = 0.f; float4 nd = make_float4(0, 0, 0, 0); unsigned bmask = 0; bool pred_k = false;
    const float cy = (float)y0 + 15.5f, cx = (float)x0 + 15.5f;
    const float R = 21.95f;
    if (t < NN) {
        float2 p = g_pts[b * NN + t];
        float w  = g_wid[b * NN + t];
        nd = make_float4(p.x, p.y, w, 0.f);
        float dy = p.x - cy, dx = p.y - cx;
        float cd = sqrtf(dy * dy + dx * dx);
        lb = cd - R - w;
        ur[t] = cd + R - w;
    }
    __syncthreads();
    if (t < 64) ur[t] = fminf(ur[t], ur[t + 64]);
    __syncthreads();
    if (t < 32) {
        float v = fminf(ur[t], ur[t + 32]);
#pragma unroll
        for (int s = 16; s > 0; s >>= 1) v = fminf(v, __shfl_xor_sync(0xffffffffu, v, s));
        if (t == 0) ublim = fminf(v, 15.0f) + 0.02f;
    }
    __syncthreads();

    if (t < NN) {
        pred_k = lb < ublim;
        bmask = __ballot_sync(0xffffffffu, pred_k);
        if ((t & 31) == 0) wcnt[t >> 5] = __popc(bmask);
    }
    __syncthreads();
    if (t == 0) {
        int o = 0;
#pragma unroll
        for (int w = 0; w < 4; w++) { wofs[w] = o; o += wcnt[w]; }
        cnt = o;
    }
    __syncthreads();
    if (t < NN && pred_k) {
        int pos = wofs[t >> 5] + __popc(bmask & ((1u << (t & 31)) - 1u));
        keep[pos] = nd;
    }
    __syncthreads();

    const int n = cnt;
    const int y  = y0 + (t >> 3);
    const int xg = x0 + (t & 7) * 4;
    const float fy = (float)y, fx0 = (float)xg;
    const float mub = ublim;
    float m0 = mub, m1 = mub, m2 = mub, m3 = mub;

    for (int k = 0; k < n; k++) {
        float4 kk = keep[k];
        float dy  = fy - kk.x;
        float dy2 = dy * dy;
        float dx0 = fx0 - kk.y;
        float dx1 = dx0 + 1.f, dx2 = dx0 + 2.f, dx3 = dx0 + 3.f;
        float d20 = fmaf(dx0, dx0, dy2);
        float d21 = fmaf(dx1, dx1, dy2);
        float d22 = fmaf(dx2, dx2, dy2);
        float d23 = fmaf(dx3, dx3, dy2);
        float t0 = m0 + kk.z, t1 = m1 + kk.z, t2 = m2 + kk.z, t3 = m3 + kk.z;
        bool imp = (t0 > 0.f && d20 < t0 * t0) || (t1 > 0.f && d21 < t1 * t1) ||
                   (t2 > 0.f && d22 < t2 * t2) || (t3 > 0.f && d23 < t3 * t3);
        if (__any_sync(0xffffffffu, imp)) {
            m0 = fminf(m0, fsqrt_approx(d20) - kk.z);
            m1 = fminf(m1, fsqrt_approx(d21) - kk.z);
            m2 = fminf(m2, fsqrt_approx(d22) - kk.z);
            m3 = fminf(m3, fsqrt_approx(d23) - kk.z);
        }
    }
    m0 = fminf(fmaxf(m0, 0.f), 15.f);
    m1 = fminf(fmaxf(m1, 0.f), 15.f);
    m2 = fminf(fmaxf(m2, 0.f), 15.f);
    m3 = fminf(fmaxf(m3, 0.f), 15.f);

    const float4 pv = *reinterpret_cast<const float4*>(pred + (b * HH + y) * WW + xg);
    float e0 = pv.x - m0, e1 = pv.y - m1, e2 = pv.z - m2, e3 = pv.w - m3;
    float e = e0 * e0 + e1 * e1 + e2 * e2 + e3 * e3;

    __shared__ float red[256];
    red[t] = e;
    __syncthreads();
    if (t < 128) red[t] += red[t + 128];
    __syncthreads();
    if (t < 64) red[t] += red[t + 64];
    __syncthreads();
    if (t < 32) {
        float v = red[t] + red[t + 32];
#pragma unroll
        for (int s = 16; s > 0; s >>= 1) v += __shfl_down_sync(0xffffffffu, v, s);
        if (t == 0) g_part[(b * 12 + blockIdx.y) * 12 + blockIdx.x] = v;
    }

    __shared__ bool amLast;
    if (t == 0) {
        __threadfence();
        unsigned v = atomicAdd(&g_cnt, 1u);
        amLast = (v == 575u);
    }
    __syncthreads();
    if (amLast) {
        __shared__ double sh[256];
        double s = 0.0;
        for (int idx = t; idx < 576; idx += 256) s += (double)g_part[idx];
        sh[t] = s;
        __syncthreads();
        for (int st = 128; st > 0; st >>= 1) {
            if (t < st) sh[t] += sh[t + st];
            __syncthreads();
        }
        if (t == 0) out[0] = (float)(sh[0] / (double)(BATCH * HH * WW));
    }
}

// ---------------- launcher ----------------
extern "C" void kernel_launch(void* const* d_in, const int* in_sizes, int n_in,
                              void* d_out, int out_size) {
    const float* pred  = (const float*)d_in[0];
    const float* nodes = (const float*)d_in[1];
    float* out = (float*)d_out;
    (void)in_sizes; (void)n_in; (void)out_size;

    prep_kernel<<<640, 512>>>(pred);
    snake_kernel<<<BATCH, 256>>>(nodes);
    render_kernel<<<dim3(12, 12, BATCH), 256>>>(pred, out);
}